// round 1
// baseline (speedup 1.0000x reference)
#include <cuda_runtime.h>
#include <cuda_bf16.h>

#define BB 4096
#define SS 200
#define DD 64
#define HH 36
#define NROWS (BB * SS)

// Scratch (allocation-free rule: __device__ globals)
__device__ float g_h[(size_t)BB * SS * HH];   // 118 MB: pre-BN hidden activations
__device__ float g_part[72 * BB];             // transposed [72][B]: per-block partial sum/sumsq
__device__ float g_tot[72];
__device__ float g_scale[HH];
__device__ float g_shift[HH];

// ---- packed f32x2 helpers (Blackwell FFMA2 via PTX) ----
__device__ __forceinline__ unsigned long long pack2(float a) {
    unsigned long long r;
    asm("mov.b64 %0, {%1, %1};" : "=l"(r) : "f"(a));
    return r;
}
__device__ __forceinline__ void fma2(unsigned long long& d, unsigned long long a, unsigned long long b) {
    asm("fma.rn.f32x2 %0, %1, %2, %3;" : "=l"(d) : "l"(a), "l"(b), "l"(d));
}
__device__ __forceinline__ float2 unpack2(unsigned long long v) {
    float2 f;
    asm("mov.b64 {%0, %1}, %2;" : "=f"(f.x), "=f"(f.y) : "l"(v));
    return f;
}

// =====================================================================
// Pass 1: per-batch W_eff build, h = c_term + hist @ W_eff, store h,
//         deterministic per-block stats partials.
// Dynamic smem: hist tile (200x65 padded) | W_eff (64x36) | c_term (36) | cand (64)
// =====================================================================
__global__ __launch_bounds__(256) void pass1_kernel(
    const float* __restrict__ history,
    const float* __restrict__ cand,
    const float* __restrict__ W1,
    const float* __restrict__ b1)
{
    extern __shared__ float smem[];
    float* sh_hist = smem;                    // 200*65 = 13000 floats
    float* sh_W    = smem + 13000;            // 64*36  = 2304 floats (16B aligned)
    float* sh_c    = smem + 13000 + 2304;     // 36 floats (8B aligned)
    float* sh_cand = sh_c + 36;               // 64 floats

    const int b   = blockIdx.x;
    const int tid = threadIdx.x;

    if (tid < DD) sh_cand[tid] = cand[b * DD + tid];
    __syncthreads();

    // W_eff[k][j] = W1[64+k][j] - W1[128+k][j] + cand[k]*W1[192+k][j]
    for (int idx = tid; idx < DD * HH; idx += 256) {
        int k = idx / HH;
        int j = idx - k * HH;
        float ck = sh_cand[k];
        sh_W[idx] = W1[(64 + k) * HH + j] - W1[(128 + k) * HH + j] + ck * W1[(192 + k) * HH + j];
    }
    // c_term[j] = b1[j] + sum_k cand[k]*(W1[k][j] + W1[128+k][j])
    if (tid < HH) {
        float s = b1[tid];
        #pragma unroll 4
        for (int k = 0; k < DD; k++)
            s += sh_cand[k] * (W1[k * HH + tid] + W1[(128 + k) * HH + tid]);
        sh_c[tid] = s;
    }
    // history tile, coalesced float4 loads, pad rows to 65 floats (conflict-free)
    {
        const float4* h4 = (const float4*)(history + (size_t)b * SS * DD);
        for (int i4 = tid; i4 < SS * DD / 4; i4 += 256) {
            int s  = i4 >> 4;
            int k4 = i4 & 15;
            float4 v = h4[i4];
            float* p = sh_hist + s * 65 + k4 * 4;
            p[0] = v.x; p[1] = v.y; p[2] = v.z; p[3] = v.w;
        }
    }
    __syncthreads();

    // compute h row (36 outputs as 18 packed f32x2 accumulators)
    unsigned long long acc[18];
    if (tid < SS) {
        const unsigned long long* cterm2 = (const unsigned long long*)sh_c;
        #pragma unroll
        for (int q = 0; q < 18; q++) acc[q] = cterm2[q];

        const float* hrow = sh_hist + tid * 65;
        const ulonglong2* Wb = (const ulonglong2*)sh_W;
        #pragma unroll 4
        for (int k = 0; k < DD; k++) {
            unsigned long long hk = pack2(hrow[k]);
            const ulonglong2* Wk = Wb + k * 9;
            #pragma unroll
            for (int q = 0; q < 9; q++) {
                ulonglong2 w = Wk[q];
                fma2(acc[2 * q],     hk, w.x);
                fma2(acc[2 * q + 1], hk, w.y);
            }
        }
    }
    __syncthreads();  // done reading sh_hist; safe to reuse as h staging

    float* sh_h = sh_hist;  // 200*36 = 7200 floats (fits in 13000)
    if (tid < SS) {
        float* dst = sh_h + tid * HH;
        #pragma unroll
        for (int q = 0; q < 18; q++) {
            float2 f = unpack2(acc[q]);
            dst[2 * q]     = f.x;
            dst[2 * q + 1] = f.y;
        }
    }
    __syncthreads();

    // coalesced store of h to global scratch
    {
        float* gh = g_h + (size_t)b * SS * HH;
        for (int i = tid; i < SS * HH; i += 256) gh[i] = sh_h[i];
    }
    // per-feature partial sums (deterministic: fixed order, one writer per slot)
    if (tid < 72) {
        int j = (tid < HH) ? tid : tid - HH;
        bool sq = (tid >= HH);
        float s = 0.f;
        #pragma unroll 4
        for (int r = 0; r < SS; r++) {
            float v = sh_h[r * HH + j];
            s += sq ? v * v : v;
        }
        g_part[tid * BB + b] = s;
    }
}

// =====================================================================
// Reduction of partials: one block per (feature, kind) column, contiguous reads.
// =====================================================================
__global__ void reduce_kernel()
{
    __shared__ float red[256];
    const int j = blockIdx.x;  // 0..71
    const float* p = g_part + j * BB;
    float s = 0.f;
    for (int i = threadIdx.x; i < BB; i += 256) s += p[i];
    red[threadIdx.x] = s;
    __syncthreads();
    for (int st = 128; st > 0; st >>= 1) {
        if (threadIdx.x < st) red[threadIdx.x] += red[threadIdx.x + st];
        __syncthreads();
    }
    if (threadIdx.x == 0) g_tot[j] = red[0];
}

__global__ void scalify_kernel(const float* __restrict__ gamma, const float* __restrict__ beta)
{
    int j = threadIdx.x;
    if (j < HH) {
        const float invn = 1.f / (float)NROWS;
        float mu  = g_tot[j] * invn;
        float var = g_tot[HH + j] * invn - mu * mu;
        float sc  = gamma[j] * rsqrtf(var + 1e-5f);
        g_scale[j] = sc;
        g_shift[j] = beta[j] - mu * sc;
    }
}

// =====================================================================
// Pass 2: BN affine + Dice + W2 -> per-row weight w; weighted pooling.
// =====================================================================
__global__ __launch_bounds__(256) void pass2_kernel(
    const float* __restrict__ history,
    const float* __restrict__ alpha,
    const float* __restrict__ W2,
    const float* __restrict__ b2,
    float* __restrict__ out)
{
    __shared__ float sh_h[SS * 37];   // pad 37 for conflict-free row reads
    __shared__ float sh_w[SS];
    __shared__ float sh_pool[256];
    __shared__ float sh_sc[HH], sh_sf[HH], sh_w2[HH];
    __shared__ float sh_al, sh_b2;

    const int b   = blockIdx.x;
    const int tid = threadIdx.x;

    {
        const float* gh = g_h + (size_t)b * SS * HH;
        for (int i = tid; i < SS * HH; i += 256) {
            int s = i / HH;
            int j = i - s * HH;
            sh_h[s * 37 + j] = gh[i];
        }
    }
    if (tid < HH) { sh_sc[tid] = g_scale[tid]; sh_sf[tid] = g_shift[tid]; sh_w2[tid] = W2[tid]; }
    if (tid == 0) { sh_al = alpha[0]; sh_b2 = b2[0]; }
    __syncthreads();

    if (tid < SS) {
        float hn[HH];
        float m = 0.f, m2 = 0.f;
        const float* hr = sh_h + tid * 37;
        #pragma unroll
        for (int j = 0; j < HH; j++) {
            float v = hr[j] * sh_sc[j] + sh_sf[j];
            hn[j] = v;
            m  += v;
            m2 += v * v;
        }
        m *= (1.f / (float)HH);
        float var = m2 * (1.f / (float)HH) - m * m;
        float inv = rsqrtf(var + 1e-3f);
        float al = sh_al;
        float w = sh_b2;
        #pragma unroll
        for (int j = 0; j < HH; j++) {
            float t  = (hn[j] - m) * inv;
            float ps = 1.f / (1.f + __expf(-t));
            w += hn[j] * (al + ps * (1.f - al)) * sh_w2[j];
        }
        sh_w[tid] = w;
    }
    __syncthreads();

    // pooling: out[b,d] = sum_s w[s] * hist[b,s,d]; 4 s-groups x 64 d lanes
    const int sg = tid >> 6;
    const int d  = tid & 63;
    const float* hb = history + (size_t)b * SS * DD;
    float acc = 0.f;
    for (int s = sg; s < SS; s += 4) acc += sh_w[s] * hb[s * DD + d];
    sh_pool[tid] = acc;
    __syncthreads();
    if (tid < 64)
        out[b * DD + tid] = sh_pool[tid] + sh_pool[tid + 64] + sh_pool[tid + 128] + sh_pool[tid + 192];
}

extern "C" void kernel_launch(void* const* d_in, const int* in_sizes, int n_in,
                              void* d_out, int out_size)
{
    const float* history = (const float*)d_in[0];
    const float* cand    = (const float*)d_in[1];
    const float* W1      = (const float*)d_in[2];
    const float* b1      = (const float*)d_in[3];
    const float* gamma   = (const float*)d_in[4];
    const float* beta    = (const float*)d_in[5];
    const float* alpha   = (const float*)d_in[6];
    const float* W2      = (const float*)d_in[7];
    const float* b2      = (const float*)d_in[8];
    float* out = (float*)d_out;

    const size_t smem1 = (size_t)(13000 + 2304 + 36 + 64) * sizeof(float);  // 61616 B
    cudaFuncSetAttribute(pass1_kernel, cudaFuncAttributeMaxDynamicSharedMemorySize, (int)smem1);

    pass1_kernel<<<BB, 256, smem1>>>(history, cand, W1, b1);
    reduce_kernel<<<72, 256>>>();
    scalify_kernel<<<1, 64>>>(gamma, beta);
    pass2_kernel<<<BB, 256>>>(history, alpha, W2, b2, out);
}